// round 2
// baseline (speedup 1.0000x reference)
#include <cuda_runtime.h>
#include <cuda_bf16.h>
#include <math.h>

// Problem constants
#define BATCH   2
#define SEQ     2048
#define EMBED   1024
#define HEADS   16
#define HDIM    64
#define TOKENS  (BATCH * SEQ)        // 4096
#define QKV_COLS (3 * EMBED)         // 3072

// ---------------- scratch (device globals: allocation-free) ----------------
__device__ float g_qkv[(size_t)TOKENS * QKV_COLS];   // [4096, 3072]
__device__ float g_att[(size_t)TOKENS * EMBED];      // [4096, 1024]

// ---------------- generic tiled SGEMM with bias ----------------
// C[M,N] = A[M,K] @ B[K,N] + bias[N].  Row-major everywhere.
// 64x64 tile, BK=16, 256 threads, 4x4 micro-tile per thread.
#define TM 64
#define TN 64
#define TK 16

__global__ void sgemm_bias(const float* __restrict__ A,
                           const float* __restrict__ B,
                           const float* __restrict__ bias,
                           float* __restrict__ C,
                           int M, int N, int K) {
    __shared__ float As[TK][TM + 1];
    __shared__ float Bs[TK][TN + 1];

    const int tid = threadIdx.x;          // 0..255
    const int tx  = tid & 15;             // 0..15 -> 4 cols each
    const int ty  = tid >> 4;             // 0..15 -> 4 rows each
    const int rowBase = blockIdx.y * TM;
    const int colBase = blockIdx.x * TN;

    float acc[4][4];
#pragma unroll
    for (int i = 0; i < 4; i++)
#pragma unroll
        for (int j = 0; j < 4; j++) acc[i][j] = 0.f;

    for (int k0 = 0; k0 < K; k0 += TK) {
        // Load A tile: 64x16 = 1024 elems, 4 per thread
#pragma unroll
        for (int t = 0; t < 4; t++) {
            int idx = tid + t * 256;
            int m = idx >> 4;
            int kk = idx & 15;
            As[kk][m] = A[(size_t)(rowBase + m) * K + (k0 + kk)];
        }
        // Load B tile: 16x64 = 1024 elems
#pragma unroll
        for (int t = 0; t < 4; t++) {
            int idx = tid + t * 256;
            int kk = idx >> 6;
            int n = idx & 63;
            Bs[kk][n] = B[(size_t)(k0 + kk) * N + (colBase + n)];
        }
        __syncthreads();

#pragma unroll
        for (int kk = 0; kk < TK; kk++) {
            float a[4], b[4];
#pragma unroll
            for (int i = 0; i < 4; i++) a[i] = As[kk][ty * 4 + i];
#pragma unroll
            for (int j = 0; j < 4; j++) b[j] = Bs[kk][tx * 4 + j];
#pragma unroll
            for (int i = 0; i < 4; i++)
#pragma unroll
                for (int j = 0; j < 4; j++) acc[i][j] += a[i] * b[j];
        }
        __syncthreads();
    }

#pragma unroll
    for (int i = 0; i < 4; i++) {
        int m = rowBase + ty * 4 + i;
#pragma unroll
        for (int j = 0; j < 4; j++) {
            int n = colBase + tx * 4 + j;
            C[(size_t)m * N + n] = acc[i][j] + bias[n];
        }
    }
}

// ---------------- flash attention (fp32, online softmax) ----------------
// grid: (B*H, SEQ/64), block: 256 threads.
// Q tile: 64 rows x 64 (resident, pre-scaled).  KV tiles: 32 rows.
// Thread layout for S (64x32): ty -> 4 rows, tx -> 2 cols.
// Thread layout for O (64x64): ty -> 4 rows, tx -> 4 cols.
__global__ void flash_attn(const float* __restrict__ qkv,
                           float* __restrict__ out) {
    __shared__ float Qs[64][65];
    __shared__ float Ks[32][65];
    __shared__ float Vs[32][65];
    __shared__ float Ps[64][33];

    const int tid = threadIdx.x;
    const int tx  = tid & 15;
    const int ty  = tid >> 4;
    const int bh  = blockIdx.x;
    const int b   = bh >> 4;
    const int h   = bh & 15;
    const int qbase = blockIdx.y * 64;
    const float scale = 0.125f;               // 1/sqrt(64)
    const size_t tokBase = (size_t)b * SEQ;

    // Load Q tile (pre-scaled)
    for (int idx = tid; idx < 64 * 64; idx += 256) {
        int r = idx >> 6, d = idx & 63;
        Qs[r][d] = qkv[(tokBase + qbase + r) * QKV_COLS + h * HDIM + d] * scale;
    }

    float m_i[4], l_i[4], O[4][4];
#pragma unroll
    for (int i = 0; i < 4; i++) {
        m_i[i] = -1e30f;
        l_i[i] = 0.f;
#pragma unroll
        for (int j = 0; j < 4; j++) O[i][j] = 0.f;
    }
    __syncthreads();

    for (int kb = 0; kb < SEQ; kb += 32) {
        // Load K,V tiles (32 rows x 64)
        for (int idx = tid; idx < 32 * 64; idx += 256) {
            int r = idx >> 6, d = idx & 63;
            size_t base = (tokBase + kb + r) * QKV_COLS + h * HDIM + d;
            Ks[r][d] = qkv[base + EMBED];        // K block
            Vs[r][d] = qkv[base + 2 * EMBED];    // V block
        }
        __syncthreads();

        // S = Q K^T : each thread 4 rows x 2 cols
        float S[4][2];
#pragma unroll
        for (int i = 0; i < 4; i++) { S[i][0] = 0.f; S[i][1] = 0.f; }
#pragma unroll 8
        for (int d = 0; d < 64; d++) {
            float a[4], kk[2];
#pragma unroll
            for (int i = 0; i < 4; i++) a[i] = Qs[ty * 4 + i][d];
#pragma unroll
            for (int j = 0; j < 2; j++) kk[j] = Ks[tx * 2 + j][d];
#pragma unroll
            for (int i = 0; i < 4; i++) {
                S[i][0] += a[i] * kk[0];
                S[i][1] += a[i] * kk[1];
            }
        }

        // Online softmax update (row-wise; 16 tx lanes own one row jointly)
#pragma unroll
        for (int i = 0; i < 4; i++) {
            float rmax = fmaxf(S[i][0], S[i][1]);
#pragma unroll
            for (int off = 8; off >= 1; off >>= 1)
                rmax = fmaxf(rmax, __shfl_xor_sync(0xffffffffu, rmax, off, 16));
            float m_new = fmaxf(m_i[i], rmax);
            float fac = expf(m_i[i] - m_new);
            float p0 = expf(S[i][0] - m_new);
            float p1 = expf(S[i][1] - m_new);
            float rsum = p0 + p1;
#pragma unroll
            for (int off = 8; off >= 1; off >>= 1)
                rsum += __shfl_xor_sync(0xffffffffu, rsum, off, 16);
            l_i[i] = l_i[i] * fac + rsum;
            m_i[i] = m_new;
#pragma unroll
            for (int j = 0; j < 4; j++) O[i][j] *= fac;
            Ps[ty * 4 + i][tx * 2 + 0] = p0;
            Ps[ty * 4 + i][tx * 2 + 1] = p1;
        }
        __syncthreads();

        // O += P @ V : each thread 4 rows x 4 D-cols
#pragma unroll 8
        for (int kv = 0; kv < 32; kv++) {
            float p[4], v[4];
#pragma unroll
            for (int i = 0; i < 4; i++) p[i] = Ps[ty * 4 + i][kv];
#pragma unroll
            for (int j = 0; j < 4; j++) v[j] = Vs[kv][tx * 4 + j];
#pragma unroll
            for (int i = 0; i < 4; i++)
#pragma unroll
                for (int j = 0; j < 4; j++) O[i][j] += p[i] * v[j];
        }
        __syncthreads();
    }

    // Normalize and write out[b, row, h*64 + d]
#pragma unroll
    for (int i = 0; i < 4; i++) {
        float inv_l = 1.0f / l_i[i];
        size_t row = tokBase + qbase + ty * 4 + i;
#pragma unroll
        for (int j = 0; j < 4; j++) {
            out[row * EMBED + h * HDIM + tx * 4 + j] = O[i][j] * inv_l;
        }
    }
}

// ---------------- launch ----------------
extern "C" void kernel_launch(void* const* d_in, const int* in_sizes, int n_in,
                              void* d_out, int out_size) {
    const float* x      = (const float*)d_in[0];   // [2,2048,1024]
    const float* W_qkv  = (const float*)d_in[1];   // [1024,3072]
    const float* b_qkv  = (const float*)d_in[2];   // [3072]
    const float* W_proj = (const float*)d_in[3];   // [1024,1024]
    const float* b_proj = (const float*)d_in[4];   // [1024]
    float* out          = (float*)d_out;           // [2,2048,1024]

    float* qkv = nullptr;
    float* att = nullptr;
    cudaGetSymbolAddress((void**)&qkv, g_qkv);
    cudaGetSymbolAddress((void**)&att, g_att);

    // 1) QKV GEMM + bias: [4096,1024] @ [1024,3072]
    {
        dim3 grid(QKV_COLS / TN, TOKENS / TM);
        sgemm_bias<<<grid, 256>>>(x, W_qkv, b_qkv, qkv, TOKENS, QKV_COLS, EMBED);
    }
    // 2) Flash attention
    {
        dim3 grid(BATCH * HEADS, SEQ / 64);
        flash_attn<<<grid, 256>>>(qkv, att);
    }
    // 3) Output projection + bias: [4096,1024] @ [1024,1024]
    {
        dim3 grid(EMBED / TN, TOKENS / TM);
        sgemm_bias<<<grid, 256>>>(att, W_proj, b_proj, out, TOKENS, EMBED, EMBED);
    }
}

// round 3
// speedup vs baseline: 4.1454x; 4.1454x over previous
#include <cuda_runtime.h>
#include <cuda_bf16.h>
#include <math.h>
#include <stdint.h>

// Problem constants
#define BATCH   2
#define SEQ     2048
#define EMBED   1024
#define HEADS   16
#define HDIM    64
#define TOKENS  (BATCH * SEQ)        // 4096
#define QKV_COLS (3 * EMBED)         // 3072

// ---------------- scratch (device globals: allocation-free) ----------------
__device__ float g_qkv[(size_t)TOKENS * QKV_COLS];   // [4096, 3072]
__device__ float g_att[(size_t)TOKENS * EMBED];      // [4096, 1024]

// ---------------- tf32 helpers ----------------
__device__ __forceinline__ uint32_t f2tf32(float x) {
    uint32_t r;
    asm("cvt.rna.tf32.f32 %0, %1;" : "=r"(r) : "f"(x));
    return r;
}

__device__ __forceinline__ void mma_tf32(float c[4],
                                         uint32_t a0, uint32_t a1, uint32_t a2, uint32_t a3,
                                         uint32_t b0, uint32_t b1) {
    asm volatile(
        "mma.sync.aligned.m16n8k8.row.col.f32.tf32.tf32.f32 "
        "{%0,%1,%2,%3}, {%4,%5,%6,%7}, {%8,%9}, {%0,%1,%2,%3};"
        : "+f"(c[0]), "+f"(c[1]), "+f"(c[2]), "+f"(c[3])
        : "r"(a0), "r"(a1), "r"(a2), "r"(a3), "r"(b0), "r"(b1));
}

// ============================================================================
// tf32 tensor-core GEMM:  C[M,N] = A[M,K] @ B[K,N] + bias[N]
// Block tile 128x128, BK=32, 256 threads = 8 warps, warp tile 32x64.
// ============================================================================
#define GAS 36    // As row stride (36 % 32 == 4 -> conflict-free A-pattern reads)
#define GBS 136   // Bs row stride (136 % 32 == 8 -> conflict-free B-pattern reads)

__global__ __launch_bounds__(256) void gemm_tf32(const float* __restrict__ A,
                                                 const float* __restrict__ B,
                                                 const float* __restrict__ bias,
                                                 float* __restrict__ C,
                                                 int M, int N, int K) {
    __shared__ uint32_t As[128 * GAS];   // [m][k], k-stride 1
    __shared__ uint32_t Bs[32 * GBS];    // [k][n], n-stride 1

    const int tid  = threadIdx.x;
    const int wid  = tid >> 5;
    const int lane = tid & 31;
    const int lq   = lane >> 2;      // lane/4
    const int lr   = lane & 3;       // lane%4

    const int wrow = (wid & 3) * 32;     // warp row within block (4 warps down)
    const int wcol = (wid >> 2) * 64;    // warp col within block (2 warps across)

    const int rowBase = blockIdx.y * 128;
    const int colBase = blockIdx.x * 128;

    float c[2][8][4];
#pragma unroll
    for (int mt = 0; mt < 2; mt++)
#pragma unroll
        for (int nt = 0; nt < 8; nt++)
#pragma unroll
            for (int i = 0; i < 4; i++) c[mt][nt][i] = 0.f;

    for (int k0 = 0; k0 < K; k0 += 32) {
        // Load A tile 128x32 (1024 float4 / 256 threads = 4 each)
#pragma unroll
        for (int t = 0; t < 4; t++) {
            int idx = tid + t * 256;
            int r  = idx >> 3;
            int c4 = idx & 7;
            float4 v = *(const float4*)&A[(size_t)(rowBase + r) * K + k0 + c4 * 4];
            uint4 u = make_uint4(f2tf32(v.x), f2tf32(v.y), f2tf32(v.z), f2tf32(v.w));
            *(uint4*)&As[r * GAS + c4 * 4] = u;
        }
        // Load B tile 32x128
#pragma unroll
        for (int t = 0; t < 4; t++) {
            int idx = tid + t * 256;
            int kk = idx >> 5;
            int c4 = idx & 31;
            float4 v = *(const float4*)&B[(size_t)(k0 + kk) * N + colBase + c4 * 4];
            uint4 u = make_uint4(f2tf32(v.x), f2tf32(v.y), f2tf32(v.z), f2tf32(v.w));
            *(uint4*)&Bs[kk * GBS + c4 * 4] = u;
        }
        __syncthreads();

#pragma unroll
        for (int ks = 0; ks < 4; ks++) {
            uint32_t a[2][4];
#pragma unroll
            for (int mt = 0; mt < 2; mt++) {
                int rb = wrow + mt * 16;
                a[mt][0] = As[(rb + lq) * GAS + ks * 8 + lr];
                a[mt][1] = As[(rb + lq + 8) * GAS + ks * 8 + lr];
                a[mt][2] = As[(rb + lq) * GAS + ks * 8 + lr + 4];
                a[mt][3] = As[(rb + lq + 8) * GAS + ks * 8 + lr + 4];
            }
            uint32_t b[8][2];
#pragma unroll
            for (int nt = 0; nt < 8; nt++) {
                int cb = wcol + nt * 8 + lq;
                b[nt][0] = Bs[(ks * 8 + lr) * GBS + cb];
                b[nt][1] = Bs[(ks * 8 + lr + 4) * GBS + cb];
            }
#pragma unroll
            for (int mt = 0; mt < 2; mt++)
#pragma unroll
                for (int nt = 0; nt < 8; nt++)
                    mma_tf32(c[mt][nt], a[mt][0], a[mt][1], a[mt][2], a[mt][3],
                             b[nt][0], b[nt][1]);
        }
        __syncthreads();
    }

    // Epilogue: add bias, write float2 pairs
#pragma unroll
    for (int mt = 0; mt < 2; mt++) {
        int r0 = rowBase + wrow + mt * 16 + lq;
#pragma unroll
        for (int nt = 0; nt < 8; nt++) {
            int cc = colBase + wcol + nt * 8 + 2 * lr;
            float b0 = bias[cc], b1 = bias[cc + 1];
            *(float2*)&C[(size_t)r0 * N + cc] =
                make_float2(c[mt][nt][0] + b0, c[mt][nt][1] + b1);
            *(float2*)&C[(size_t)(r0 + 8) * N + cc] =
                make_float2(c[mt][nt][2] + b0, c[mt][nt][3] + b1);
        }
    }
}

// ============================================================================
// tf32 tensor-core flash attention.
// grid (B*H, SEQ/128), 256 threads = 8 warps; each warp owns a 16-row strip.
// Q tile 128x64 (pre-scaled), KV tile 64x64, online softmax in C-fragments.
// ============================================================================
#define QS_S 68   // 68 % 32 == 4 : A-pattern conflict-free
#define KS_S 68
#define PS_S 68
#define VS_S 72   // 72 % 32 == 8 : B-pattern conflict-free

__global__ __launch_bounds__(256) void flash_attn_tc(const float* __restrict__ qkv,
                                                     float* __restrict__ out) {
    extern __shared__ uint32_t sm[];
    uint32_t* Qs = sm;                        // 128*68
    uint32_t* Ks = Qs + 128 * QS_S;           // 64*68
    uint32_t* Vs = Ks + 64 * KS_S;            // 64*72
    uint32_t* Ps = Vs + 64 * VS_S;            // 128*68

    const int tid  = threadIdx.x;
    const int wid  = tid >> 5;
    const int lane = tid & 31;
    const int lq   = lane >> 2;
    const int lr   = lane & 3;

    const int bh = blockIdx.x;
    const int b  = bh >> 4;
    const int h  = bh & 15;
    const int qbase = blockIdx.y * 128;
    const size_t tokBase = (size_t)b * SEQ;
    const int wrow = wid * 16;

    // Load Q tile (pre-scaled by 1/8), convert tf32
#pragma unroll
    for (int t = 0; t < 8; t++) {
        int idx = tid + t * 256;
        int r  = idx >> 4;
        int c4 = idx & 15;
        float4 v = *(const float4*)&qkv[(tokBase + qbase + r) * QKV_COLS + h * HDIM + c4 * 4];
        uint4 u = make_uint4(f2tf32(v.x * 0.125f), f2tf32(v.y * 0.125f),
                             f2tf32(v.z * 0.125f), f2tf32(v.w * 0.125f));
        *(uint4*)&Qs[r * QS_S + c4 * 4] = u;
    }

    float o[8][4];
#pragma unroll
    for (int nt = 0; nt < 8; nt++)
#pragma unroll
        for (int i = 0; i < 4; i++) o[nt][i] = 0.f;
    float m0 = -1e30f, m1 = -1e30f, l0 = 0.f, l1 = 0.f;

    for (int kb = 0; kb < SEQ; kb += 64) {
        __syncthreads();   // protect Ks/Vs/Ps from previous iteration's readers
        // Load K and V tiles (64x64 each)
#pragma unroll
        for (int t = 0; t < 4; t++) {
            int idx = tid + t * 256;
            int r  = idx >> 4;
            int c4 = idx & 15;
            size_t base = (tokBase + kb + r) * QKV_COLS + h * HDIM + c4 * 4;
            float4 kv4 = *(const float4*)&qkv[base + EMBED];
            *(uint4*)&Ks[r * KS_S + c4 * 4] =
                make_uint4(f2tf32(kv4.x), f2tf32(kv4.y), f2tf32(kv4.z), f2tf32(kv4.w));
            float4 vv4 = *(const float4*)&qkv[base + 2 * EMBED];
            *(uint4*)&Vs[r * VS_S + c4 * 4] =
                make_uint4(f2tf32(vv4.x), f2tf32(vv4.y), f2tf32(vv4.z), f2tf32(vv4.w));
        }
        __syncthreads();

        // S = Q @ K^T  (16 x 64 per warp), k-dim = 64 -> 8 k-steps
        float s[8][4];
#pragma unroll
        for (int nt = 0; nt < 8; nt++)
#pragma unroll
            for (int i = 0; i < 4; i++) s[nt][i] = 0.f;

#pragma unroll
        for (int ks = 0; ks < 8; ks++) {
            uint32_t a0 = Qs[(wrow + lq) * QS_S + ks * 8 + lr];
            uint32_t a1 = Qs[(wrow + lq + 8) * QS_S + ks * 8 + lr];
            uint32_t a2 = Qs[(wrow + lq) * QS_S + ks * 8 + lr + 4];
            uint32_t a3 = Qs[(wrow + lq + 8) * QS_S + ks * 8 + lr + 4];
#pragma unroll
            for (int nt = 0; nt < 8; nt++) {
                uint32_t b0 = Ks[(nt * 8 + lq) * KS_S + ks * 8 + lr];
                uint32_t b1 = Ks[(nt * 8 + lq) * KS_S + ks * 8 + lr + 4];
                mma_tf32(s[nt], a0, a1, a2, a3, b0, b1);
            }
        }

        // Online softmax (rows r0 = wrow+lq via c0/c1, r1 = r0+8 via c2/c3)
        float rmax0 = -1e30f, rmax1 = -1e30f;
#pragma unroll
        for (int nt = 0; nt < 8; nt++) {
            rmax0 = fmaxf(rmax0, fmaxf(s[nt][0], s[nt][1]));
            rmax1 = fmaxf(rmax1, fmaxf(s[nt][2], s[nt][3]));
        }
        rmax0 = fmaxf(rmax0, __shfl_xor_sync(0xffffffffu, rmax0, 1));
        rmax0 = fmaxf(rmax0, __shfl_xor_sync(0xffffffffu, rmax0, 2));
        rmax1 = fmaxf(rmax1, __shfl_xor_sync(0xffffffffu, rmax1, 1));
        rmax1 = fmaxf(rmax1, __shfl_xor_sync(0xffffffffu, rmax1, 2));

        float mn0 = fmaxf(m0, rmax0);
        float mn1 = fmaxf(m1, rmax1);
        float fac0 = __expf(m0 - mn0);
        float fac1 = __expf(m1 - mn1);

        float rsum0 = 0.f, rsum1 = 0.f;
        int r0 = wrow + lq;
#pragma unroll
        for (int nt = 0; nt < 8; nt++) {
            float p0 = __expf(s[nt][0] - mn0);
            float p1 = __expf(s[nt][1] - mn0);
            float p2 = __expf(s[nt][2] - mn1);
            float p3 = __expf(s[nt][3] - mn1);
            rsum0 += p0 + p1;
            rsum1 += p2 + p3;
            int cc = nt * 8 + 2 * lr;
            *(uint2*)&Ps[r0 * PS_S + cc] =
                make_uint2(f2tf32(p0), f2tf32(p1));
            *(uint2*)&Ps[(r0 + 8) * PS_S + cc] =
                make_uint2(f2tf32(p2), f2tf32(p3));
        }
        rsum0 += __shfl_xor_sync(0xffffffffu, rsum0, 1);
        rsum0 += __shfl_xor_sync(0xffffffffu, rsum0, 2);
        rsum1 += __shfl_xor_sync(0xffffffffu, rsum1, 1);
        rsum1 += __shfl_xor_sync(0xffffffffu, rsum1, 2);

        l0 = l0 * fac0 + rsum0;
        l1 = l1 * fac1 + rsum1;
        m0 = mn0;
        m1 = mn1;

        // Rescale O accumulators
#pragma unroll
        for (int nt = 0; nt < 8; nt++) {
            o[nt][0] *= fac0; o[nt][1] *= fac0;
            o[nt][2] *= fac1; o[nt][3] *= fac1;
        }
        __syncthreads();   // Ps visible to all warps (only own strip used, but keep ordered)

        // O += P @ V  (k-dim = 64 kv positions -> 8 k-steps)
#pragma unroll
        for (int ks = 0; ks < 8; ks++) {
            uint32_t a0 = Ps[(wrow + lq) * PS_S + ks * 8 + lr];
            uint32_t a1 = Ps[(wrow + lq + 8) * PS_S + ks * 8 + lr];
            uint32_t a2 = Ps[(wrow + lq) * PS_S + ks * 8 + lr + 4];
            uint32_t a3 = Ps[(wrow + lq + 8) * PS_S + ks * 8 + lr + 4];
#pragma unroll
            for (int nt = 0; nt < 8; nt++) {
                uint32_t b0 = Vs[(ks * 8 + lr) * VS_S + nt * 8 + lq];
                uint32_t b1 = Vs[(ks * 8 + lr + 4) * VS_S + nt * 8 + lq];
                mma_tf32(o[nt], a0, a1, a2, a3, b0, b1);
            }
        }
    }

    // Normalize and write out[b, row, h*64 + col]
    float inv0 = 1.0f / l0;
    float inv1 = 1.0f / l1;
    size_t row0 = tokBase + qbase + wrow + lq;
#pragma unroll
    for (int nt = 0; nt < 8; nt++) {
        int cc = h * HDIM + nt * 8 + 2 * lr;
        *(float2*)&out[row0 * EMBED + cc] =
            make_float2(o[nt][0] * inv0, o[nt][1] * inv0);
        *(float2*)&out[(row0 + 8) * EMBED + cc] =
            make_float2(o[nt][2] * inv1, o[nt][3] * inv1);
    }
}

// ---------------- launch ----------------
extern "C" void kernel_launch(void* const* d_in, const int* in_sizes, int n_in,
                              void* d_out, int out_size) {
    const float* x      = (const float*)d_in[0];   // [2,2048,1024]
    const float* W_qkv  = (const float*)d_in[1];   // [1024,3072]
    const float* b_qkv  = (const float*)d_in[2];   // [3072]
    const float* W_proj = (const float*)d_in[3];   // [1024,1024]
    const float* b_proj = (const float*)d_in[4];   // [1024]
    float* out          = (float*)d_out;           // [2,2048,1024]

    float* qkv = nullptr;
    float* att = nullptr;
    cudaGetSymbolAddress((void**)&qkv, g_qkv);
    cudaGetSymbolAddress((void**)&att, g_att);

    // attention dynamic smem: (128*68)*2 + 64*68 + 64*72 words
    const int attn_smem = (128 * QS_S * 2 + 64 * KS_S + 64 * VS_S) * 4;
    static bool attr_set = false;
    if (!attr_set) {
        cudaFuncSetAttribute(flash_attn_tc,
                             cudaFuncAttributeMaxDynamicSharedMemorySize, attn_smem);
        attr_set = true;
    }

    // 1) QKV GEMM + bias: [4096,1024] @ [1024,3072]
    {
        dim3 grid(QKV_COLS / 128, TOKENS / 128);
        gemm_tf32<<<grid, 256>>>(x, W_qkv, b_qkv, qkv, TOKENS, QKV_COLS, EMBED);
    }
    // 2) Flash attention
    {
        dim3 grid(BATCH * HEADS, SEQ / 128);
        flash_attn_tc<<<grid, 256, attn_smem>>>(qkv, att);
    }
    // 3) Output projection + bias: [4096,1024] @ [1024,1024]
    {
        dim3 grid(EMBED / 128, TOKENS / 128);
        gemm_tf32<<<grid, 256>>>(att, W_proj, b_proj, out, TOKENS, EMBED, EMBED);
    }
}